// round 15
// baseline (speedup 1.0000x reference)
#include <cuda_runtime.h>
#include <cuda_fp16.h>

// ---------------------------------------------------------------------------
// LowrankLearnableHash, round 15: round-14 base (best: 102.5us) + PDL overlap.
//   prep_all signals griddepcontrol.launch_dependents; lrh_main is launched
//   with programmatic stream serialization, front-loads pts loads + all plane
//   index/weight ALU, then griddepcontrol.wait before the first gather.
//   lrh_main math is bit-identical to round 14.
//
//   g_plane_dup entry (128 B stride, 96 B used = 3 sectors), per (y0,x0):
//     chunk0 @  0: [pair0 | pair4], chunk1 @ 32: [pair1 | pair5],
//     chunk2 @ 64: [pair2 | pair3]; pair = 4 x half2 [c00,c01,c10,c11].
//   Lane k: one v8 .cg load at chunk min(k,2); lane3 uses hi half (p3).
//   g_feat_h: [64^3*32] fp16 channel-last; HFMA2 dz-split, fp32 merge.
// ---------------------------------------------------------------------------

namespace {
constexpr int RESO = 256;
constexpr int NTEX = RESO * RESO;
constexpr int ESTRIDE_H = 64;          // entry stride in halfs (128 B)
constexpr int FR   = 64;
constexpr int FD   = 32;
constexpr int NVOX = FR * FR * FR;
constexpr int DUP_BLOCKS  = 3 * (NTEX / 256);   // 768
constexpr int FEAT_BLOCKS = NVOX / 256;         // 1024
}

__device__ __align__(256) __half g_plane_dup[3][NTEX * ESTRIDE_H]; // 24 MB
__device__ __align__(256) __half g_feat_h[NVOX * FD];              // 16 MB

// ---------------------------------------------------------------------------
// Merged prep: dup table + feature transpose. Signals dependents at block end.
// ---------------------------------------------------------------------------
__global__ void prep_all(const float* __restrict__ p0,
                         const float* __restrict__ p1,
                         const float* __restrict__ p2,
                         const float* __restrict__ f) {
    int b = blockIdx.x;
    if (b < DUP_BLOCKS) {
        int pl = b / (NTEX / 256);
        int e  = (b % (NTEX / 256)) * 256 + threadIdx.x;
        const float* src = (pl == 0) ? p0 : ((pl == 1) ? p1 : p2);

        int y = e >> 8, x = e & 255;
        int x1 = min(x + 1, RESO - 1);
        int y1 = min(y + 1, RESO - 1);
        int i00 = y  * RESO + x,  i01 = y  * RESO + x1;
        int i10 = y1 * RESO + x,  i11 = y1 * RESO + x1;

        const int off_h[6] = {0, 16, 32, 40, 8, 24};  // pair p -> half offset

        struct alignas(16) Slice { __half2 h[4]; };
        __half* dst = &g_plane_dup[pl][(size_t)e * ESTRIDE_H];

#pragma unroll
        for (int p = 0; p < 6; ++p) {
            const float* c0 = src + (2 * p) * NTEX;
            const float* c1 = src + (2 * p + 1) * NTEX;
            Slice s;
            s.h[0] = __floats2half2_rn(c0[i00], c1[i00]);
            s.h[1] = __floats2half2_rn(c0[i01], c1[i01]);
            s.h[2] = __floats2half2_rn(c0[i10], c1[i10]);
            s.h[3] = __floats2half2_rn(c0[i11], c1[i11]);
            *reinterpret_cast<uint4*>(dst + off_h[p]) = *reinterpret_cast<uint4*>(&s);
        }
        uint4 z = make_uint4(0u, 0u, 0u, 0u);
        *reinterpret_cast<uint4*>(dst + 48) = z;
        *reinterpret_cast<uint4*>(dst + 56) = z;
    } else {
        int v = (b - DUP_BLOCKS) * 256 + threadIdx.x;
        struct alignas(32) H32 { __half h[FD]; } tmp;
#pragma unroll
        for (int c = 0; c < FD; ++c) tmp.h[c] = __float2half(f[c * NVOX + v]);
        uint4* dst = reinterpret_cast<uint4*>(&g_feat_h[(size_t)v * FD]);
        const uint4* s = reinterpret_cast<const uint4*>(&tmp);
#pragma unroll
        for (int k = 0; k < 4; ++k) dst[k] = s[k];
    }
    // allow dependent grid (lrh_main) to begin scheduling
    asm volatile("griddepcontrol.launch_dependents;");
}

// ---------------------------------------------------------------------------
__device__ __forceinline__ void ldg_v8_cg(const float* p, float f[8]) {
    asm volatile("ld.global.cg.v8.f32 {%0,%1,%2,%3,%4,%5,%6,%7}, [%8];"
                 : "=f"(f[0]), "=f"(f[1]), "=f"(f[2]), "=f"(f[3]),
                   "=f"(f[4]), "=f"(f[5]), "=f"(f[6]), "=f"(f[7])
                 : "l"(p));
}

__device__ __forceinline__ void stg_v8(float* p, const float f[8]) {
    asm volatile("st.global.v8.f32 [%0], {%1,%2,%3,%4,%5,%6,%7,%8};"
                 :: "l"(p),
                    "f"(f[0]), "f"(f[1]), "f"(f[2]), "f"(f[3]),
                    "f"(f[4]), "f"(f[5]), "f"(f[6]), "f"(f[7])
                 : "memory");
}

__device__ __forceinline__ __half2 f_as_h2(float v) {
    unsigned u = __float_as_uint(v);
    return *reinterpret_cast<__half2*>(&u);
}

__device__ __forceinline__ __half2 blend4(const float c[4], __half2 w00, __half2 w01,
                                          __half2 w10, __half2 w11) {
    __half2 r = __hmul2(f_as_h2(c[0]), w00);
    r = __hfma2(f_as_h2(c[1]), w01, r);
    r = __hfma2(f_as_h2(c[2]), w10, r);
    return __hfma2(f_as_h2(c[3]), w11, r);
}

// Phase 1 (prep-independent): entry address + bilinear weights.
struct PlaneCtx {
    const float* addr;
    __half2 w00, w01, w10, w11;
};

__device__ __forceinline__ PlaneCtx plane_ctx(const __half* __restrict__ pl,
                                              float a, float b, int co) {
    float x = fminf(fmaxf((a + 1.0f) * (0.5f * (RESO - 1)), 0.0f), (float)(RESO - 1));
    float y = fminf(fmaxf((b + 1.0f) * (0.5f * (RESO - 1)), 0.0f), (float)(RESO - 1));
    int x0 = min((int)x, RESO - 2);
    int y0 = min((int)y, RESO - 2);
    float fx = x - (float)x0;
    float fy = y - (float)y0;

    PlaneCtx c;
    c.addr = reinterpret_cast<const float*>(pl) + (size_t)(y0 * RESO + x0) * 32 + co;
    c.w00 = __float2half2_rn((1.0f - fx) * (1.0f - fy));
    c.w01 = __float2half2_rn(fx * (1.0f - fy));
    c.w10 = __float2half2_rn((1.0f - fx) * fy);
    c.w11 = __float2half2_rn(fx * fy);
    return c;
}

// Phase 2 (after griddepcontrol.wait): gather + blend.
__device__ __forceinline__ void plane_eval(const PlaneCtx& c, bool k3,
                                           __half2& rA, __half2& rB) {
    float f[8];
    ldg_v8_cg(c.addr, f);
    __half2 lo = blend4(f,     c.w00, c.w01, c.w10, c.w11);
    __half2 hi = blend4(f + 4, c.w00, c.w01, c.w10, c.w11);
    rA = k3 ? hi : lo;
    rB = hi;
}

// ---------------------------------------------------------------------------
// 4 lanes per point.
// ---------------------------------------------------------------------------
__global__ void __launch_bounds__(256) lrh_main(const float* __restrict__ pts,
                                                float* __restrict__ out, int n) {
    int t = blockIdx.x * blockDim.x + threadIdx.x;
    int i = t >> 2;
    int k = t & 3;
    if (i >= n) {
        asm volatile("griddepcontrol.wait;");
        return;
    }

    int co = 8 * min(k, 2);
    bool k3 = (k == 3);

    // prep-independent: pts loads + all plane index/weight ALU
    float px = __ldg(pts + 3 * i);
    float py = __ldg(pts + 3 * i + 1);
    float pz = __ldg(pts + 3 * i + 2);

    PlaneCtx c01 = plane_ctx(g_plane_dup[0], px, py, co);
    PlaneCtx c02 = plane_ctx(g_plane_dup[1], px, pz, co);
    PlaneCtx c12 = plane_ctx(g_plane_dup[2], py, pz, co);

    // wait for prep_all's writes, then gather
    asm volatile("griddepcontrol.wait;");

    __half2 a01, b01, a02, b02, a12, b12;
    plane_eval(c01, k3, a01, b01);
    plane_eval(c02, k3, a02, b02);
    plane_eval(c12, k3, a12, b12);

    __half2 pA = __hmul2(__hmul2(a01, a02), a12);
    __half2 pB = __hmul2(__hmul2(b01, b02), b12);

    float2 fA = __half22float2(pA);
    float2 fB = __half22float2(pB);
    float sA = fA.x + fA.y;   // lane k: pair-k product sum (lane3: p3)
    float sB = fB.x + fB.y;   // lanes 0,1: pairs 4,5 (dim2)

    sA += __shfl_xor_sync(0xffffffffu, sA, 1);  // lanes 0,1: dim0; 2,3: dim1
    sB += __shfl_xor_sync(0xffffffffu, sB, 1);  // lanes 0,1: dim2

    float cx = __shfl_sync(0xffffffffu, sA, 0, 4);
    float cy = __shfl_sync(0xffffffffu, sA, 2, 4);
    float cz = __shfl_sync(0xffffffffu, sB, 0, 4);

    // Trilinear sample of fp16 features. HFMA2, dz-split chains, fp32 merge.
    float x = fminf(fmaxf((cx + 1.0f) * (0.5f * (FR - 1)), 0.0f), (float)(FR - 1));
    float y = fminf(fmaxf((cy + 1.0f) * (0.5f * (FR - 1)), 0.0f), (float)(FR - 1));
    float z = fminf(fmaxf((cz + 1.0f) * (0.5f * (FR - 1)), 0.0f), (float)(FR - 1));
    int x0 = min((int)x, FR - 2);
    int y0 = min((int)y, FR - 2);
    int z0 = min((int)z, FR - 2);
    float fx = x - (float)x0;
    float fy = y - (float)y0;
    float fz = z - (float)z0;

    int vbase = ((z0 * FR + y0) * FR + x0) * 4 + k;
    const uint4* fb = reinterpret_cast<const uint4*>(g_feat_h) + vbase;
    constexpr int SX = 4;
    constexpr int SY = FR * 4;
    constexpr int SZ = FR * FR * 4;

    float wx[2] = {1.0f - fx, fx};
    float wy[2] = {1.0f - fy, fy};
    float wz[2] = {1.0f - fz, fz};

    __half2 acc0[4], acc1[4];
    __half2 zero = __float2half2_rn(0.0f);
#pragma unroll
    for (int m = 0; m < 4; ++m) { acc0[m] = zero; acc1[m] = zero; }

#pragma unroll
    for (int dz = 0; dz < 2; ++dz) {
#pragma unroll
        for (int dy = 0; dy < 2; ++dy) {
#pragma unroll
            for (int dx = 0; dx < 2; ++dx) {
                __half2 w = __float2half2_rn(wz[dz] * wy[dy] * wx[dx]);
                uint4 u = __ldg(fb + dz * SZ + dy * SY + dx * SX);
                const __half2* v = reinterpret_cast<const __half2*>(&u);
#pragma unroll
                for (int m = 0; m < 4; ++m) {
                    if (dz == 0) acc0[m] = __hfma2(v[m], w, acc0[m]);
                    else         acc1[m] = __hfma2(v[m], w, acc1[m]);
                }
            }
        }
    }

    float f[8];
#pragma unroll
    for (int m = 0; m < 4; ++m) {
        float2 a = __half22float2(acc0[m]);
        float2 b = __half22float2(acc1[m]);
        f[2 * m]     = a.x + b.x;
        f[2 * m + 1] = a.y + b.y;
    }

    stg_v8(out + i * FD + 8 * k, f);
}

// ---------------------------------------------------------------------------
extern "C" void kernel_launch(void* const* d_in, const int* in_sizes, int n_in,
                              void* d_out, int out_size) {
    const float* pts  = (const float*)d_in[0];
    const float* p01  = (const float*)d_in[1];
    const float* p02  = (const float*)d_in[2];
    const float* p12  = (const float*)d_in[3];
    const float* feat = (const float*)d_in[4];
    float* out = (float*)d_out;
    int n = in_sizes[0] / 3;

    prep_all<<<DUP_BLOCKS + FEAT_BLOCKS, 256>>>(p01, p02, p12, feat);

    long long threads = 4LL * n;
    int grid = (int)((threads + 255) / 256);

    cudaLaunchConfig_t cfg = {};
    cfg.gridDim  = dim3(grid, 1, 1);
    cfg.blockDim = dim3(256, 1, 1);
    cfg.dynamicSmemBytes = 0;
    cfg.stream = 0;
    cudaLaunchAttribute attr[1];
    attr[0].id = cudaLaunchAttributeProgrammaticStreamSerialization;
    attr[0].val.programmaticStreamSerializationAllowed = 1;
    cfg.attrs = attr;
    cfg.numAttrs = 1;
    cudaLaunchKernelEx(&cfg, lrh_main, pts, out, n);
}

// round 17
// speedup vs baseline: 1.1055x; 1.1055x over previous
#include <cuda_runtime.h>
#include <cuda_fp16.h>

// ---------------------------------------------------------------------------
// LowrankLearnableHash, round 17: round-14 base (best: 102.5us) +
//   (a) prep_all: drop dead 32B pad writes (bytes 96..127 never read) -18MB
//   (b) output stores st.global.cs (evict-first; protect L2 plane residency)
//   pts loads: 3x scalar __ldg (v2 was misaligned for odd i -- stride 12B).
//   lrh_main math bit-identical to round 14.
//
//   g_plane_dup entry (128 B stride, 96 B used = 3 sectors), per (y0,x0):
//     chunk0 @  0: [pair0 | pair4], chunk1 @ 32: [pair1 | pair5],
//     chunk2 @ 64: [pair2 | pair3]; pair = 4 x half2 [c00,c01,c10,c11].
//   Lane k: one v8 .cg load at chunk min(k,2); lane3 uses hi half (p3).
//   g_feat_h: [64^3*32] fp16 channel-last; HFMA2 dz-split, fp32 merge.
// ---------------------------------------------------------------------------

namespace {
constexpr int RESO = 256;
constexpr int NTEX = RESO * RESO;
constexpr int ESTRIDE_H = 64;          // entry stride in halfs (128 B)
constexpr int FR   = 64;
constexpr int FD   = 32;
constexpr int NVOX = FR * FR * FR;
constexpr int DUP_BLOCKS  = 3 * (NTEX / 256);   // 768
constexpr int FEAT_BLOCKS = NVOX / 256;         // 1024
}

__device__ __align__(256) __half g_plane_dup[3][NTEX * ESTRIDE_H]; // 24 MB
__device__ __align__(256) __half g_feat_h[NVOX * FD];              // 16 MB

// ---------------------------------------------------------------------------
// Merged prep: dup table + feature transpose. No pad writes (never read).
// ---------------------------------------------------------------------------
__global__ void prep_all(const float* __restrict__ p0,
                         const float* __restrict__ p1,
                         const float* __restrict__ p2,
                         const float* __restrict__ f) {
    int b = blockIdx.x;
    if (b < DUP_BLOCKS) {
        int pl = b / (NTEX / 256);
        int e  = (b % (NTEX / 256)) * 256 + threadIdx.x;
        const float* src = (pl == 0) ? p0 : ((pl == 1) ? p1 : p2);

        int y = e >> 8, x = e & 255;
        int x1 = min(x + 1, RESO - 1);
        int y1 = min(y + 1, RESO - 1);
        int i00 = y  * RESO + x,  i01 = y  * RESO + x1;
        int i10 = y1 * RESO + x,  i11 = y1 * RESO + x1;

        const int off_h[6] = {0, 16, 32, 40, 8, 24};  // pair p -> half offset

        struct alignas(16) Slice { __half2 h[4]; };
        __half* dst = &g_plane_dup[pl][(size_t)e * ESTRIDE_H];

#pragma unroll
        for (int p = 0; p < 6; ++p) {
            const float* c0 = src + (2 * p) * NTEX;
            const float* c1 = src + (2 * p + 1) * NTEX;
            Slice s;
            s.h[0] = __floats2half2_rn(c0[i00], c1[i00]);
            s.h[1] = __floats2half2_rn(c0[i01], c1[i01]);
            s.h[2] = __floats2half2_rn(c0[i10], c1[i10]);
            s.h[3] = __floats2half2_rn(c0[i11], c1[i11]);
            *reinterpret_cast<uint4*>(dst + off_h[p]) = *reinterpret_cast<uint4*>(&s);
        }
        // bytes 96..127 are never read by lrh_main: no pad writes.
    } else {
        int v = (b - DUP_BLOCKS) * 256 + threadIdx.x;
        struct alignas(32) H32 { __half h[FD]; } tmp;
#pragma unroll
        for (int c = 0; c < FD; ++c) tmp.h[c] = __float2half(f[c * NVOX + v]);
        uint4* dst = reinterpret_cast<uint4*>(&g_feat_h[(size_t)v * FD]);
        const uint4* s = reinterpret_cast<const uint4*>(&tmp);
#pragma unroll
        for (int k = 0; k < 4; ++k) dst[k] = s[k];
    }
}

// ---------------------------------------------------------------------------
__device__ __forceinline__ void ldg_v8_cg(const float* p, float f[8]) {
    asm volatile("ld.global.cg.v8.f32 {%0,%1,%2,%3,%4,%5,%6,%7}, [%8];"
                 : "=f"(f[0]), "=f"(f[1]), "=f"(f[2]), "=f"(f[3]),
                   "=f"(f[4]), "=f"(f[5]), "=f"(f[6]), "=f"(f[7])
                 : "l"(p));
}

__device__ __forceinline__ void stg_v8_cs(float* p, const float f[8]) {
    asm volatile("st.global.cs.v8.f32 [%0], {%1,%2,%3,%4,%5,%6,%7,%8};"
                 :: "l"(p),
                    "f"(f[0]), "f"(f[1]), "f"(f[2]), "f"(f[3]),
                    "f"(f[4]), "f"(f[5]), "f"(f[6]), "f"(f[7])
                 : "memory");
}

__device__ __forceinline__ __half2 f_as_h2(float v) {
    unsigned u = __float_as_uint(v);
    return *reinterpret_cast<__half2*>(&u);
}

__device__ __forceinline__ __half2 blend4(const float c[4], __half2 w00, __half2 w01,
                                          __half2 w10, __half2 w11) {
    __half2 r = __hmul2(f_as_h2(c[0]), w00);
    r = __hfma2(f_as_h2(c[1]), w01, r);
    r = __hfma2(f_as_h2(c[2]), w10, r);
    return __hfma2(f_as_h2(c[3]), w11, r);
}

// Sample one plane. co = hoisted chunk offset (floats), k3 = (lane==3).
__device__ __forceinline__ void sample_plane_v8(const __half* __restrict__ pl,
                                                float a, float b, int co, bool k3,
                                                __half2& rA, __half2& rB) {
    float x = fminf(fmaxf((a + 1.0f) * (0.5f * (RESO - 1)), 0.0f), (float)(RESO - 1));
    float y = fminf(fmaxf((b + 1.0f) * (0.5f * (RESO - 1)), 0.0f), (float)(RESO - 1));
    int x0 = min((int)x, RESO - 2);
    int y0 = min((int)y, RESO - 2);
    float fx = x - (float)x0;
    float fy = y - (float)y0;

    __half2 w00 = __float2half2_rn((1.0f - fx) * (1.0f - fy));
    __half2 w01 = __float2half2_rn(fx * (1.0f - fy));
    __half2 w10 = __float2half2_rn((1.0f - fx) * fy);
    __half2 w11 = __float2half2_rn(fx * fy);

    const float* entry = reinterpret_cast<const float*>(pl) + (size_t)(y0 * RESO + x0) * 32;
    float f[8];
    ldg_v8_cg(entry + co, f);

    __half2 lo = blend4(f,     w00, w01, w10, w11);
    __half2 hi = blend4(f + 4, w00, w01, w10, w11);
    rA = k3 ? hi : lo;   // single 32-bit select
    rB = hi;             // dead in lanes 2,3
}

// ---------------------------------------------------------------------------
// 4 lanes per point.
// ---------------------------------------------------------------------------
__global__ void __launch_bounds__(256) lrh_main(const float* __restrict__ pts,
                                                float* __restrict__ out, int n) {
    int t = blockIdx.x * blockDim.x + threadIdx.x;
    int i = t >> 2;
    int k = t & 3;
    if (i >= n) return;

    int co = 8 * min(k, 2);       // hoisted chunk offset
    bool k3 = (k == 3);

    float px = __ldg(pts + 3 * i);
    float py = __ldg(pts + 3 * i + 1);
    float pz = __ldg(pts + 3 * i + 2);

    __half2 a01, b01, a02, b02, a12, b12;
    sample_plane_v8(g_plane_dup[0], px, py, co, k3, a01, b01);
    sample_plane_v8(g_plane_dup[1], px, pz, co, k3, a02, b02);
    sample_plane_v8(g_plane_dup[2], py, pz, co, k3, a12, b12);

    __half2 pA = __hmul2(__hmul2(a01, a02), a12);
    __half2 pB = __hmul2(__hmul2(b01, b02), b12);

    float2 fA = __half22float2(pA);
    float2 fB = __half22float2(pB);
    float sA = fA.x + fA.y;   // lane k: pair-k product sum (lane3: p3)
    float sB = fB.x + fB.y;   // lanes 0,1: pairs 4,5 (dim2)

    sA += __shfl_xor_sync(0xffffffffu, sA, 1);  // lanes 0,1: dim0; 2,3: dim1
    sB += __shfl_xor_sync(0xffffffffu, sB, 1);  // lanes 0,1: dim2

    float cx = __shfl_sync(0xffffffffu, sA, 0, 4);
    float cy = __shfl_sync(0xffffffffu, sA, 2, 4);
    float cz = __shfl_sync(0xffffffffu, sB, 0, 4);

    // Trilinear sample of fp16 features. HFMA2, dz-split chains, fp32 merge.
    float x = fminf(fmaxf((cx + 1.0f) * (0.5f * (FR - 1)), 0.0f), (float)(FR - 1));
    float y = fminf(fmaxf((cy + 1.0f) * (0.5f * (FR - 1)), 0.0f), (float)(FR - 1));
    float z = fminf(fmaxf((cz + 1.0f) * (0.5f * (FR - 1)), 0.0f), (float)(FR - 1));
    int x0 = min((int)x, FR - 2);
    int y0 = min((int)y, FR - 2);
    int z0 = min((int)z, FR - 2);
    float fx = x - (float)x0;
    float fy = y - (float)y0;
    float fz = z - (float)z0;

    int vbase = ((z0 * FR + y0) * FR + x0) * 4 + k;
    const uint4* fb = reinterpret_cast<const uint4*>(g_feat_h) + vbase;
    constexpr int SX = 4;
    constexpr int SY = FR * 4;
    constexpr int SZ = FR * FR * 4;

    float wx[2] = {1.0f - fx, fx};
    float wy[2] = {1.0f - fy, fy};
    float wz[2] = {1.0f - fz, fz};

    __half2 acc0[4], acc1[4];
    __half2 zero = __float2half2_rn(0.0f);
#pragma unroll
    for (int m = 0; m < 4; ++m) { acc0[m] = zero; acc1[m] = zero; }

#pragma unroll
    for (int dz = 0; dz < 2; ++dz) {
#pragma unroll
        for (int dy = 0; dy < 2; ++dy) {
#pragma unroll
            for (int dx = 0; dx < 2; ++dx) {
                __half2 w = __float2half2_rn(wz[dz] * wy[dy] * wx[dx]);
                uint4 u = __ldg(fb + dz * SZ + dy * SY + dx * SX);
                const __half2* v = reinterpret_cast<const __half2*>(&u);
#pragma unroll
                for (int m = 0; m < 4; ++m) {
                    if (dz == 0) acc0[m] = __hfma2(v[m], w, acc0[m]);
                    else         acc1[m] = __hfma2(v[m], w, acc1[m]);
                }
            }
        }
    }

    float f[8];
#pragma unroll
    for (int m = 0; m < 4; ++m) {
        float2 a = __half22float2(acc0[m]);
        float2 b = __half22float2(acc1[m]);
        f[2 * m]     = a.x + b.x;
        f[2 * m + 1] = a.y + b.y;
    }

    stg_v8_cs(out + i * FD + 8 * k, f);
}

// ---------------------------------------------------------------------------
extern "C" void kernel_launch(void* const* d_in, const int* in_sizes, int n_in,
                              void* d_out, int out_size) {
    const float* pts  = (const float*)d_in[0];
    const float* p01  = (const float*)d_in[1];
    const float* p02  = (const float*)d_in[2];
    const float* p12  = (const float*)d_in[3];
    const float* feat = (const float*)d_in[4];
    float* out = (float*)d_out;
    int n = in_sizes[0] / 3;

    prep_all<<<DUP_BLOCKS + FEAT_BLOCKS, 256>>>(p01, p02, p12, feat);
    long long threads = 4LL * n;
    lrh_main<<<(int)((threads + 255) / 256), 256>>>(pts, out, n);
}